// round 17
// baseline (speedup 1.0000x reference)
#include <cuda_runtime.h>

#define NN 8192
#define INDIM 512
#define HID 50
#define ZD 128
#define NCAT 64
#define EPSV 1e-8f
#define NWORK_MAX (NN/32 + NCAT)
#define NFX (NN/32)
#define NFZ (NN/32)

// uneg dynamic smem (floats): R12 proven layout
//  phase1: FxsTd [128][68] = 8704 | Wst [32][132] = 4224  (12928)
//  phase2: Us    [32][128] = 4096 | Fs  [64][132] = 8448  (12544)
#define UNEG_SMEM_FLOATS 12928
#define UNEG_SMEM_BYTES  (UNEG_SMEM_FLOATS*4)

typedef unsigned long long u64;

// ---------------- scratch ----------------------------------------------------
__device__ float g_fx[NN*ZD];    // natural order
__device__ float g_fz[NN*ZD];    // natural order
__device__ int   g_cnt[NCAT], g_start[NCAT];
__device__ int   g_sorted[NN];
__device__ int   g_work[NWORK_MAX];
__device__ int   g_nwork;

// ---------------- f32x2 helpers ----------------------------------------------
__device__ __forceinline__ u64 dup2(float x){
    u64 r; asm("mov.b64 %0, {%1, %1};" : "=l"(r) : "f"(x)); return r;
}
__device__ __forceinline__ void fma2(u64 &d, u64 a, u64 b){
    asm("fma.rn.f32x2 %0, %1, %2, %0;" : "+l"(d) : "l"(a), "l"(b));
}
__device__ __forceinline__ float2 unpk(u64 v){
    float2 f; asm("mov.b64 {%0, %1}, %2;" : "=f"(f.x), "=f"(f.y) : "l"(v)); return f;
}
__device__ __forceinline__ float softplusf(float v){
    return fmaxf(v, 0.f) + log1pf(__expf(-fabsf(v)));
}

// ---------------- prep: block0 = bucket, blocks 1..512 = fx/fz ---------------
__global__ void prep_kernel(const float* __restrict__ x,  const float* __restrict__ W1,
                            const float* __restrict__ b1, const float* __restrict__ W2,
                            const float* __restrict__ b2, const float* __restrict__ z,
                            const float* __restrict__ Wz, const float* __restrict__ bz,
                            const int*   __restrict__ c){
    __shared__ __align__(16) float sbuf[9800];
    __shared__ float aux128[128];
    __shared__ float aux64[64];
    __shared__ int   s_cnt[NCAT];
    __shared__ int   s_cursor[NCAT];
    int tid  = threadIdx.x;
    int lane = tid & 31;

    if (blockIdx.x == 0){
        // ================= bucket sort (warp-aggregated atomics) =============
        if (tid < NCAT) s_cnt[tid] = 0;
        __syncthreads();
        for (int i = tid; i < NN; i += 256){
            int cc = min(max(c[i], 0), NCAT - 1);
            unsigned m = __match_any_sync(0xffffffffu, cc);
            if ((m & ((1u << lane) - 1)) == 0) atomicAdd(&s_cnt[cc], __popc(m));
        }
        __syncthreads();
        if (tid == 0){
            int s = 0, w = 0;
            for (int cc = 0; cc < NCAT; cc++){
                s_cursor[cc] = s;
                g_start[cc]  = s;
                int n = s_cnt[cc];
                g_cnt[cc] = n;
                s += n;
                int nt = (n + 31) >> 5;
                for (int t = 0; t < nt; t++) g_work[w++] = (cc << 16) | t;
            }
            g_nwork = w;
        }
        __syncthreads();
        for (int i = tid; i < NN; i += 256){
            int cc = min(max(c[i], 0), NCAT - 1);
            unsigned m = __match_any_sync(0xffffffffu, cc);
            int leader = __ffs(m) - 1;
            int rank   = __popc(m & ((1u << lane) - 1));
            int base   = 0;
            if (lane == leader) base = atomicAdd(&s_cursor[cc], __popc(m));
            base = __shfl_sync(0xffffffffu, base, leader);
            g_sorted[base + rank] = i;
        }
    } else if (blockIdx.x <= NFX){
        // ===== fx = relu(x@W1+b1)@W2+b2, 32 rows, dup-A layouts =====
        float* ATd  = sbuf;            // [32][68] k-major dup rows: 2176
        float* Bs   = sbuf + 2176;     // [32][64]: 2048
        float* HsTd = sbuf;            // [50][68] dup rows: 3400 (overlaps, after sync)
        float* W2s  = sbuf + 3400;     // [50][128]: 6400
        float* b1s  = aux64;
        float* b2s  = aux128;

        int row0 = (blockIdx.x - 1) * 32;
        if (tid < 64)  b1s[tid] = (tid < HID) ? b1[tid] : 0.f;
        if (tid < 128) b2s[tid] = b2[tid];

        // preload W2 into registers
        float4 w2r[7];
        #pragma unroll
        for (int i = 0; i < 7; i++){
            int q = tid + 256*i;
            if (q < 1600) w2r[i] = *(const float4*)&W2[q*4];
        }

        // GEMM1 prefetch: thread = (kq = tid>>5 covering k=kq*4..+3, r = tid&31)
        int ar = tid & 31, kq = tid >> 5;
        float4 pa = *(const float4*)&x[(size_t)(row0 + ar)*INDIM + kq*4];
        float pb[8];
        #pragma unroll
        for (int i = 0; i < 8; i++){
            int e = tid + 256*i;
            int k = e >> 6, j = e & 63;
            pb[i] = (j < HID) ? W1[(size_t)k*HID + j] : 0.f;
        }

        int rg = (tid >> 4) * 2;     // rows rg, rg+1
        int cg = (tid & 15) * 4;     // cols cg..cg+3
        u64 acc2[2][2] = {};         // [row][colpair]

        for (int t = 0; t < 16; t++){
            __syncthreads();
            {   // store A transposed + duplicated (float2 dup-stores)
                int kb = kq*4;
                float2 d0 = make_float2(pa.x, pa.x);
                float2 d1 = make_float2(pa.y, pa.y);
                float2 d2 = make_float2(pa.z, pa.z);
                float2 d3 = make_float2(pa.w, pa.w);
                *(float2*)&ATd[(kb+0)*68 + 2*ar] = d0;
                *(float2*)&ATd[(kb+1)*68 + 2*ar] = d1;
                *(float2*)&ATd[(kb+2)*68 + 2*ar] = d2;
                *(float2*)&ATd[(kb+3)*68 + 2*ar] = d3;
            }
            #pragma unroll
            for (int i = 0; i < 8; i++){
                int e = tid + 256*i;
                Bs[(e >> 6)*64 + (e & 63)] = pb[i];
            }
            __syncthreads();
            if (t < 15){
                int k0 = (t+1)*32;
                pa = *(const float4*)&x[(size_t)(row0 + ar)*INDIM + k0 + kq*4];
                #pragma unroll
                for (int i = 0; i < 8; i++){
                    int e = tid + 256*i;
                    int k = e >> 6, j = e & 63;
                    pb[i] = (j < HID) ? W1[(size_t)(k0 + k)*HID + j] : 0.f;
                }
            }
            #pragma unroll
            for (int k = 0; k < 32; k++){
                u64 a01x = *(const u64*)&ATd[k*68 + 2*rg];        // dup(rg)
                u64 a01y = *(const u64*)&ATd[k*68 + 2*rg + 2];    // dup(rg+1)
                ulonglong2 bb = *(const ulonglong2*)&Bs[k*64 + cg];
                fma2(acc2[0][0], a01x, bb.x); fma2(acc2[0][1], a01x, bb.y);
                fma2(acc2[1][0], a01y, bb.x); fma2(acc2[1][1], a01y, bb.y);
            }
        }
        __syncthreads();             // GEMM1 smem reads done

        // hidden (ReLU+bias) -> HsTd transposed + dup
        #pragma unroll
        for (int i = 0; i < 2; i++){
            float2 p0 = unpk(acc2[i][0]);
            float2 p1 = unpk(acc2[i][1]);
            float hv[4] = {p0.x, p0.y, p1.x, p1.y};
            #pragma unroll
            for (int j = 0; j < 4; j++){
                int cc = cg + j;
                if (cc < HID){
                    float h = fmaxf(hv[j] + b1s[cc], 0.f);
                    *(float2*)&HsTd[cc*68 + 2*(rg+i)] = make_float2(h, h);
                }
            }
        }
        #pragma unroll
        for (int i = 0; i < 7; i++){
            int q = tid + 256*i;
            if (q < 1600) *(float4*)&W2s[q*4] = w2r[i];
        }
        __syncthreads();

        // GEMM2: 32x128, K=50; 4 rows x 4 cols per thread, dup-A broadcasts
        {
            int r0 = (tid >> 5) * 4;     // warp-uniform
            int c0 = (tid & 31) * 4;
            u64 a2[4][2] = {};
            #pragma unroll
            for (int h = 0; h < HID; h++){
                const float* hp = &HsTd[h*68 + 2*r0];
                ulonglong2 A01 = *(const ulonglong2*)hp;        // dup(r0), dup(r0+1)
                ulonglong2 A23 = *(const ulonglong2*)(hp + 4);  // dup(r0+2), dup(r0+3)
                ulonglong2 B   = *(const ulonglong2*)&W2s[h*128 + c0];
                fma2(a2[0][0], A01.x, B.x); fma2(a2[0][1], A01.x, B.y);
                fma2(a2[1][0], A01.y, B.x); fma2(a2[1][1], A01.y, B.y);
                fma2(a2[2][0], A23.x, B.x); fma2(a2[2][1], A23.x, B.y);
                fma2(a2[3][0], A23.y, B.x); fma2(a2[3][1], A23.y, B.y);
            }
            #pragma unroll
            for (int i = 0; i < 4; i++){
                float2 p0 = unpk(a2[i][0]);
                float2 p1 = unpk(a2[i][1]);
                float4 v = make_float4(p0.x + b2s[c0], p0.y + b2s[c0+1],
                                       p1.x + b2s[c0+2], p1.y + b2s[c0+3]);
                *(float4*)&g_fx[(size_t)((tid >> 5)*4 + (blockIdx.x - 1)*32 + i)*ZD + c0] = v;
            }
        }
    } else {
        // ===== fz = z@Wz+bz, 32 rows (R12 proven) =====
        float* Zs  = sbuf;            // [32][36]
        float* Wzt = sbuf + 1152;     // [32][132]
        float* bzs = aux128;

        int row0 = (blockIdx.x - 1 - NFX) * 32;
        if (tid < 128) bzs[tid] = bz[tid];

        int ar = tid >> 3, ac4 = tid & 7;
        float4 pz = *(const float4*)&z[(size_t)(row0 + ar)*ZD + ac4*4];
        float4 pw[4];
        #pragma unroll
        for (int i = 0; i < 4; i++){
            int q = tid + 256*i;
            pw[i] = *(const float4*)&Wz[(size_t)(q >> 5)*ZD + (q & 31)*4];
        }

        int rg = (tid >> 4) * 2;
        int cg = (tid & 15) * 4;
        u64 acc2[2][4] = {};

        for (int kt = 0; kt < 4; kt++){
            __syncthreads();
            *(float4*)&Zs[ar*36 + ac4*4] = pz;
            #pragma unroll
            for (int i = 0; i < 4; i++){
                int q = tid + 256*i;
                *(float4*)&Wzt[(q >> 5)*132 + (q & 31)*4] = pw[i];
            }
            __syncthreads();
            if (kt < 3){
                int k0 = (kt+1)*32;
                pz = *(const float4*)&z[(size_t)(row0 + ar)*ZD + k0 + ac4*4];
                #pragma unroll
                for (int i = 0; i < 4; i++){
                    int q = tid + 256*i;
                    pw[i] = *(const float4*)&Wz[(size_t)(k0 + (q >> 5))*ZD + (q & 31)*4];
                }
            }
            #pragma unroll
            for (int k = 0; k < 32; k++){
                u64 da0 = dup2(Zs[rg*36 + k]);
                u64 da1 = dup2(Zs[(rg+1)*36 + k]);
                ulonglong2 b0 = *(const ulonglong2*)&Wzt[k*132 + cg];
                ulonglong2 b1 = *(const ulonglong2*)&Wzt[k*132 + cg + 64];
                fma2(acc2[0][0], da0, b0.x); fma2(acc2[0][1], da0, b0.y);
                fma2(acc2[0][2], da0, b1.x); fma2(acc2[0][3], da0, b1.y);
                fma2(acc2[1][0], da1, b0.x); fma2(acc2[1][1], da1, b0.y);
                fma2(acc2[1][2], da1, b1.x); fma2(acc2[1][3], da1, b1.y);
            }
        }

        #pragma unroll
        for (int i = 0; i < 2; i++){
            size_t base = (size_t)(row0 + rg + i)*ZD;
            float2 p0 = unpk(acc2[i][0]), p1 = unpk(acc2[i][1]);
            float2 p2 = unpk(acc2[i][2]), p3 = unpk(acc2[i][3]);
            *(float4*)&g_fz[base + cg] =
                make_float4(p0.x + bzs[cg],   p0.y + bzs[cg+1],
                            p1.x + bzs[cg+2], p1.y + bzs[cg+3]);
            *(float4*)&g_fz[base + cg + 64] =
                make_float4(p2.x + bzs[cg+64], p2.y + bzs[cg+65],
                            p3.x + bzs[cg+66], p3.y + bzs[cg+67]);
        }
    }
}

// ---------------- fused u + neg + output (exact R12, proven 36.4us) ----------
__global__ void __launch_bounds__(256)
uneg_kernel(const float* __restrict__ Ws, float* __restrict__ out){
    extern __shared__ __align__(16) float dyn[];
    __shared__ float Ts[32];
    __shared__ int   gidx[32];
    float* FxsTd = dyn;          // [128][68]
    float* Wst   = dyn + 8704;   // [32][132]
    float* Us    = dyn;          // [32][128]
    float* Fs    = dyn + 4096;   // [64][132]

    int w = blockIdx.x;
    if (w >= g_nwork) return;
    int item  = g_work[w];
    int cat   = item >> 16, tile = item & 0xffff;
    int start = g_start[cat], cnt = g_cnt[cat];
    int i0    = tile * 32;
    int ni    = min(32, cnt - i0);
    int tid   = threadIdx.x;

    if (tid < 32) gidx[tid] = (tid < ni) ? g_sorted[start + i0 + tid] : 0;

    // stage fx tile transposed + DUPLICATED
    {
        int r = tid & 31, kg = tid >> 5;
        int gi = 0; bool act = (r < ni);
        if (act) gi = g_sorted[start + i0 + r];
        const float4* src = (const float4*)&g_fx[(size_t)gi*ZD + kg*16];
        #pragma unroll
        for (int q = 0; q < 4; q++){
            float4 v = act ? src[q] : make_float4(0.f,0.f,0.f,0.f);
            int kb = kg*16 + q*4;
            FxsTd[(kb+0)*68 + 2*r] = v.x; FxsTd[(kb+0)*68 + 2*r + 1] = v.x;
            FxsTd[(kb+1)*68 + 2*r] = v.y; FxsTd[(kb+1)*68 + 2*r + 1] = v.y;
            FxsTd[(kb+2)*68 + 2*r] = v.z; FxsTd[(kb+2)*68 + 2*r + 1] = v.z;
            FxsTd[(kb+3)*68 + 2*r] = v.w; FxsTd[(kb+3)*68 + 2*r + 1] = v.w;
        }
    }

    const float* Wc = Ws + (size_t)cat*ZD*ZD;
    float4 pw[4];
    #pragma unroll
    for (int i = 0; i < 4; i++){
        int q = tid + 256*i;
        pw[i] = *(const float4*)&Wc[(size_t)(q >> 5)*ZD + (q & 31)*4];
    }
    // prefetch first 64-row Fs tile (gathered)
    float4 pf[8];
    {
        int nj0 = min(64, cnt);
        #pragma unroll
        for (int i = 0; i < 8; i++){
            int q = tid + 256*i;
            int r = q >> 5;
            pf[i] = make_float4(0.f,0.f,0.f,0.f);
            if (r < nj0){
                int gj = g_sorted[start + r];
                pf[i] = *(const float4*)&g_fz[(size_t)gj*ZD + (q & 31)*4];
            }
        }
    }

    int r0 = (tid >> 5) * 4;     // warp-uniform row group
    int c0 = (tid & 31) * 4;
    u64 acc2[4][2] = {};

    for (int kt = 0; kt < ZD; kt += 32){
        __syncthreads();
        #pragma unroll
        for (int i = 0; i < 4; i++){
            int q = tid + 256*i;
            *(float4*)&Wst[(q >> 5)*132 + (q & 31)*4] = pw[i];
        }
        __syncthreads();
        if (kt < ZD - 32){
            #pragma unroll
            for (int i = 0; i < 4; i++){
                int q = tid + 256*i;
                pw[i] = *(const float4*)&Wc[(size_t)(kt + 32 + (q >> 5))*ZD + (q & 31)*4];
            }
        }
        #pragma unroll
        for (int k = 0; k < 32; k++){
            const float* ap = &FxsTd[(kt+k)*68 + 2*r0];
            ulonglong2 a01 = *(const ulonglong2*)ap;
            ulonglong2 a23 = *(const ulonglong2*)(ap + 4);
            ulonglong2 bb  = *(const ulonglong2*)&Wst[k*132 + c0];
            fma2(acc2[0][0], a01.x, bb.x); fma2(acc2[0][1], a01.x, bb.y);
            fma2(acc2[1][0], a01.y, bb.x); fma2(acc2[1][1], a01.y, bb.y);
            fma2(acc2[2][0], a23.x, bb.x); fma2(acc2[2][1], a23.x, bb.y);
            fma2(acc2[3][0], a23.y, bb.x); fma2(acc2[3][1], a23.y, bb.y);
        }
    }
    __syncthreads();

    #pragma unroll
    for (int i = 0; i < 4; i++){
        float2 p0 = unpk(acc2[i][0]);
        float2 p1 = unpk(acc2[i][1]);
        *(float4*)&Us[(r0+i)*128 + c0] = make_float4(p0.x, p0.y, p1.x, p1.y);
    }

    // phase 2: 64-wide j-tiles; lane jj handles j = j0+jj and j0+32+jj
    int jj = tid & 31;
    int ig = tid >> 5;
    float sum[4] = {0.f, 0.f, 0.f, 0.f};
    int nt64 = (cnt + 63) >> 6;

    for (int jt = 0; jt < nt64; jt++){
        int j0 = jt*64;
        int nj = min(64, cnt - j0);
        __syncthreads();
        #pragma unroll
        for (int i = 0; i < 8; i++){
            int q = tid + 256*i;
            *(float4*)&Fs[(q >> 5)*132 + (q & 31)*4] = pf[i];
        }
        __syncthreads();
        if (jt + 1 < nt64){
            int j0n = j0 + 64;
            int njn = min(64, cnt - j0n);
            #pragma unroll
            for (int i = 0; i < 8; i++){
                int q = tid + 256*i;
                int r = q >> 5;
                pf[i] = make_float4(0.f,0.f,0.f,0.f);
                if (r < njn){
                    int gj = g_sorted[start + j0n + r];
                    pf[i] = *(const float4*)&g_fz[(size_t)gj*ZD + (q & 31)*4];
                }
            }
        }

        u64 a1[4] = {}, a2[4] = {};
        #pragma unroll
        for (int k0 = 0; k0 < ZD; k0 += 4){
            ulonglong2 f1 = *(const ulonglong2*)&Fs[jj*132 + k0];
            ulonglong2 f2 = *(const ulonglong2*)&Fs[(jj+32)*132 + k0];
            #pragma unroll
            for (int m = 0; m < 4; m++){
                ulonglong2 u = *(const ulonglong2*)&Us[(ig*4 + m)*128 + k0];
                fma2(a1[m], u.x, f1.x); fma2(a1[m], u.y, f1.y);
                fma2(a2[m], u.x, f2.x); fma2(a2[m], u.y, f2.y);
            }
        }
        #pragma unroll
        for (int m = 0; m < 4; m++){
            float2 s1 = unpk(a1[m]); float d1 = s1.x + s1.y;
            float2 s2 = unpk(a2[m]); float d2 = s2.x + s2.y;
            int rr = ig*4 + m;
            int gd = i0 + rr;
            if (rr < ni && gd >= j0 && gd < j0 + 64 && (gd & 31) == jj)
                Ts[rr] = softplusf(((gd - j0) >> 5) ? d2 : d1);
            float v = 0.f;
            if (jj      < nj) v += softplusf(d1);
            if (jj + 32 < nj) v += softplusf(d2);
            v += __shfl_xor_sync(0xffffffffu, v, 16);
            v += __shfl_xor_sync(0xffffffffu, v, 8);
            v += __shfl_xor_sync(0xffffffffu, v, 4);
            v += __shfl_xor_sync(0xffffffffu, v, 2);
            v += __shfl_xor_sync(0xffffffffu, v, 1);
            sum[m] += v;
        }
    }
    __syncthreads();

    if (jj == 0){
        float inv = 1.f / (float)cnt;
        #pragma unroll
        for (int m = 0; m < 4; m++){
            int rr = ig*4 + m;
            if (rr < ni)
                out[gidx[rr]] = logf(Ts[rr] + EPSV) - logf(sum[m]*inv + EPSV);
        }
    }
}

// ---------------- launch ----------------------------------------------------
extern "C" void kernel_launch(void* const* d_in, const int* in_sizes, int n_in,
                              void* d_out, int out_size){
    const float* x  = (const float*)d_in[0];
    const int*   c  = (const int*)  d_in[1];
    const float* z  = (const float*)d_in[2];
    const float* W1 = (const float*)d_in[3];
    const float* b1 = (const float*)d_in[4];
    const float* W2 = (const float*)d_in[5];
    const float* b2 = (const float*)d_in[6];
    const float* Wz = (const float*)d_in[7];
    const float* bz = (const float*)d_in[8];
    const float* Ws = (const float*)d_in[9];
    float* out = (float*)d_out;

    cudaFuncSetAttribute(uneg_kernel, cudaFuncAttributeMaxDynamicSharedMemorySize,
                         UNEG_SMEM_BYTES);

    prep_kernel <<<1 + NFX + NFZ, 256>>>(x, W1, b1, W2, b2, z, Wz, bz, c);
    uneg_kernel <<<NWORK_MAX, 256, UNEG_SMEM_BYTES>>>(Ws, out);
}